// round 1
// baseline (speedup 1.0000x reference)
#include <cuda_runtime.h>
#include <cstdint>

#define SEQ   2048
#define EMB   1024
#define NH    16
#define HD    64
#define NTOK  8192      // B*S = 4*2048
#define NBH   64        // B*H

// Scratch: Q,K,V in [B,H,S,D] layout, ctx in [token, E] layout.
__device__ float g_Q[(size_t)NTOK * EMB];
__device__ float g_K[(size_t)NTOK * EMB];
__device__ float g_V[(size_t)NTOK * EMB];
__device__ float g_C[(size_t)NTOK * EMB];

// ---------------------------------------------------------------------------
// GEMM: C[m,n] = sum_k A[m,k] * W[n,k] + bias[n]   (A: [M,1024], W: [1024,1024])
// 128x128 block tile, BK=16, 256 threads, 8x8 per thread (4+4 split rows/cols).
// TRANS_OUT=1 writes to [B,H,S,D] layout (for Q/K/V), else row-major [M,E].
// ---------------------------------------------------------------------------
template<int TRANS_OUT>
__global__ void __launch_bounds__(256, 2) gemm_nt(
    const float* __restrict__ A, const float* __restrict__ W,
    const float* __restrict__ bias, float* __restrict__ Cout)
{
    __shared__ float As[16][128];   // [k][m]
    __shared__ float Ws[16][128];   // [k][n]

    const int tid  = threadIdx.x;
    const int bm   = blockIdx.y * 128;
    const int bn   = blockIdx.x * 128;
    const int tx   = tid & 15;
    const int ty   = tid >> 4;
    const int lrow = tid >> 2;          // 0..63
    const int lcol = (tid & 3) << 2;    // 0,4,8,12

    const float* A0 = A + (size_t)(bm + lrow) * EMB + lcol;
    const float* A1 = A0 + (size_t)64 * EMB;
    const float* W0 = W + (size_t)(bn + lrow) * EMB + lcol;
    const float* W1 = W0 + (size_t)64 * EMB;

    float acc[8][8];
#pragma unroll
    for (int i = 0; i < 8; i++)
#pragma unroll
        for (int j = 0; j < 8; j++) acc[i][j] = 0.f;

    for (int k0 = 0; k0 < EMB; k0 += 16) {
        float4 a0 = *(const float4*)(A0 + k0);
        float4 a1 = *(const float4*)(A1 + k0);
        float4 w0 = *(const float4*)(W0 + k0);
        float4 w1 = *(const float4*)(W1 + k0);
        __syncthreads();   // previous iteration done reading smem
        As[lcol+0][lrow]    = a0.x; As[lcol+1][lrow]    = a0.y;
        As[lcol+2][lrow]    = a0.z; As[lcol+3][lrow]    = a0.w;
        As[lcol+0][lrow+64] = a1.x; As[lcol+1][lrow+64] = a1.y;
        As[lcol+2][lrow+64] = a1.z; As[lcol+3][lrow+64] = a1.w;
        Ws[lcol+0][lrow]    = w0.x; Ws[lcol+1][lrow]    = w0.y;
        Ws[lcol+2][lrow]    = w0.z; Ws[lcol+3][lrow]    = w0.w;
        Ws[lcol+0][lrow+64] = w1.x; Ws[lcol+1][lrow+64] = w1.y;
        Ws[lcol+2][lrow+64] = w1.z; Ws[lcol+3][lrow+64] = w1.w;
        __syncthreads();
#pragma unroll
        for (int kk = 0; kk < 16; kk++) {
            float4 ra0 = *(const float4*)&As[kk][ty*4];
            float4 ra1 = *(const float4*)&As[kk][ty*4 + 64];
            float4 rb0 = *(const float4*)&Ws[kk][tx*4];
            float4 rb1 = *(const float4*)&Ws[kk][tx*4 + 64];
            float ra[8] = {ra0.x, ra0.y, ra0.z, ra0.w, ra1.x, ra1.y, ra1.z, ra1.w};
            float rb[8] = {rb0.x, rb0.y, rb0.z, rb0.w, rb1.x, rb1.y, rb1.z, rb1.w};
#pragma unroll
            for (int i = 0; i < 8; i++)
#pragma unroll
                for (int j = 0; j < 8; j++)
                    acc[i][j] = fmaf(ra[i], rb[j], acc[i][j]);
        }
    }

#pragma unroll
    for (int i = 0; i < 8; i++) {
        int m = bm + ((i < 4) ? (ty*4 + i) : (64 + ty*4 + (i - 4)));
#pragma unroll
        for (int j = 0; j < 8; j++) {
            int n = bn + ((j < 4) ? (tx*4 + j) : (64 + tx*4 + (j - 4)));
            float c = acc[i][j] + bias[n];
            if (TRANS_OUT) {
                int b = m >> 11, s = m & (SEQ - 1);
                int h = n >> 6,  d = n & 63;
                Cout[((size_t)(b * NH + h) * SEQ + s) * HD + d] = c;
            } else {
                Cout[(size_t)m * EMB + n] = c;
            }
        }
    }
}

// ---------------------------------------------------------------------------
// Fused attention: for one (b,h) and a 128-query tile, stream 128-key tiles:
//   S = Q·K^T ; P = S / (8 + |S|)  (softsign with 1/sqrt(64) scale folded in)
//   ctx += P·V   (accumulated in registers across key tiles)
// Writes ctx directly in [token, E] layout for the output projection.
// ---------------------------------------------------------------------------
#define VS_STRIDE 68
#define PS_STRIDE 132
#define ATTN_SMEM_FLOATS (64*128 + 64*128 + 128*VS_STRIDE + 128*PS_STRIDE)

__global__ void __launch_bounds__(256, 1) attn_kernel(
    const float* __restrict__ Q, const float* __restrict__ K,
    const float* __restrict__ V, float* __restrict__ Cctx)
{
    extern __shared__ float sm[];
    float* Qs = sm;                         // [d][i]  64 x 128
    float* Ks = Qs + 64 * 128;              // [d][j]  64 x 128
    float* Vs = Ks + 64 * 128;              // [j][d]  128 x 68
    float* Ps = Vs + 128 * VS_STRIDE;       // [i][j]  128 x 132

    const int tid = threadIdx.x;
    const int tx  = tid & 15;
    const int ty  = tid >> 4;
    const int bh  = blockIdx.y;             // b*16 + h
    const int q0  = blockIdx.x * 128;

    const float* Qbh = Q + (size_t)bh * SEQ * HD;
    const float* Kbh = K + (size_t)bh * SEQ * HD;
    const float* Vbh = V + (size_t)bh * SEQ * HD;

    int prow[8];
#pragma unroll
    for (int i = 0; i < 8; i++)
        prow[i] = (i < 4) ? (ty*4 + i) : (64 + ty*4 + (i - 4));

    // Load Q tile transposed: Qs[d][i]
    {
        int idx = tid;
#pragma unroll
        for (int r = 0; r < 8; r++, idx += 256) {
            int row = idx >> 4;
            int d0  = (idx & 15) << 2;
            float4 v = *(const float4*)(Qbh + (size_t)(q0 + row) * HD + d0);
            Qs[(d0+0)*128 + row] = v.x;
            Qs[(d0+1)*128 + row] = v.y;
            Qs[(d0+2)*128 + row] = v.z;
            Qs[(d0+3)*128 + row] = v.w;
        }
    }

    float acc2[8][4];
#pragma unroll
    for (int i = 0; i < 8; i++)
#pragma unroll
        for (int d = 0; d < 4; d++) acc2[i][d] = 0.f;

    for (int kt = 0; kt < SEQ; kt += 128) {
        __syncthreads();   // prev gemm2 done with Vs/Ps (covers Qs first iter)
        // Load K tile transposed Ks[d][j], V tile natural Vs[j][d]
        {
            int idx = tid;
#pragma unroll
            for (int r = 0; r < 8; r++, idx += 256) {
                int row = idx >> 4;
                int d0  = (idx & 15) << 2;
                float4 kv = *(const float4*)(Kbh + (size_t)(kt + row) * HD + d0);
                Ks[(d0+0)*128 + row] = kv.x;
                Ks[(d0+1)*128 + row] = kv.y;
                Ks[(d0+2)*128 + row] = kv.z;
                Ks[(d0+3)*128 + row] = kv.w;
                float4 vv = *(const float4*)(Vbh + (size_t)(kt + row) * HD + d0);
                *(float4*)&Vs[row * VS_STRIDE + d0] = vv;
            }
        }
        __syncthreads();

        // gemm1: S[i][j] = sum_d Qs[d][i] * Ks[d][j]
        float sacc[8][8];
#pragma unroll
        for (int i = 0; i < 8; i++)
#pragma unroll
            for (int j = 0; j < 8; j++) sacc[i][j] = 0.f;

#pragma unroll 8
        for (int d = 0; d < 64; d++) {
            float4 a0 = *(const float4*)&Qs[d*128 + ty*4];
            float4 a1 = *(const float4*)&Qs[d*128 + ty*4 + 64];
            float4 b0 = *(const float4*)&Ks[d*128 + tx*4];
            float4 b1 = *(const float4*)&Ks[d*128 + tx*4 + 64];
            float ra[8] = {a0.x, a0.y, a0.z, a0.w, a1.x, a1.y, a1.z, a1.w};
            float rb[8] = {b0.x, b0.y, b0.z, b0.w, b1.x, b1.y, b1.z, b1.w};
#pragma unroll
            for (int i = 0; i < 8; i++)
#pragma unroll
                for (int j = 0; j < 8; j++)
                    sacc[i][j] = fmaf(ra[i], rb[j], sacc[i][j]);
        }

        // softsign (scale 1/8 folded): p = s / (8 + |s|); store P[i][j]
#pragma unroll
        for (int i = 0; i < 8; i++) {
            int row = prow[i];
            float4 p0, p1;
            p0.x = sacc[i][0] / (8.f + fabsf(sacc[i][0]));
            p0.y = sacc[i][1] / (8.f + fabsf(sacc[i][1]));
            p0.z = sacc[i][2] / (8.f + fabsf(sacc[i][2]));
            p0.w = sacc[i][3] / (8.f + fabsf(sacc[i][3]));
            p1.x = sacc[i][4] / (8.f + fabsf(sacc[i][4]));
            p1.y = sacc[i][5] / (8.f + fabsf(sacc[i][5]));
            p1.z = sacc[i][6] / (8.f + fabsf(sacc[i][6]));
            p1.w = sacc[i][7] / (8.f + fabsf(sacc[i][7]));
            *(float4*)&Ps[row * PS_STRIDE + tx*4]      = p0;
            *(float4*)&Ps[row * PS_STRIDE + tx*4 + 64] = p1;
        }
        __syncthreads();

        // gemm2: ctx[i][d] += sum_j P[i][j] * V[j][d]
#pragma unroll 2
        for (int j = 0; j < 128; j++) {
            float4 rv = *(const float4*)&Vs[j * VS_STRIDE + tx*4];
            float rvv[4] = {rv.x, rv.y, rv.z, rv.w};
            float rp[8];
#pragma unroll
            for (int i = 0; i < 8; i++)
                rp[i] = Ps[prow[i] * PS_STRIDE + j];
#pragma unroll
            for (int i = 0; i < 8; i++)
#pragma unroll
                for (int d = 0; d < 4; d++)
                    acc2[i][d] = fmaf(rp[i], rvv[d], acc2[i][d]);
        }
    }

    // Write ctx in [token, E] layout: token = b*SEQ + q0 + row, col = h*64 + d
    const int b = bh >> 4, h = bh & 15;
#pragma unroll
    for (int i = 0; i < 8; i++) {
        int row = prow[i];
        float4 o = {acc2[i][0], acc2[i][1], acc2[i][2], acc2[i][3]};
        *(float4*)&Cctx[(size_t)(b * SEQ + q0 + row) * EMB + h * HD + tx*4] = o;
    }
}

// ---------------------------------------------------------------------------
extern "C" void kernel_launch(void* const* d_in, const int* in_sizes, int n_in,
                              void* d_out, int out_size)
{
    (void)in_sizes; (void)n_in; (void)out_size;
    const float* x  = (const float*)d_in[0];
    const float* Wq = (const float*)d_in[1];
    const float* bq = (const float*)d_in[2];
    const float* Wk = (const float*)d_in[3];
    const float* bk = (const float*)d_in[4];
    const float* Wv = (const float*)d_in[5];
    const float* bv = (const float*)d_in[6];
    const float* Wo = (const float*)d_in[7];
    const float* bo = (const float*)d_in[8];
    float* out = (float*)d_out;

    float *Qp, *Kp, *Vp, *Cp;
    cudaGetSymbolAddress((void**)&Qp, g_Q);
    cudaGetSymbolAddress((void**)&Kp, g_K);
    cudaGetSymbolAddress((void**)&Vp, g_V);
    cudaGetSymbolAddress((void**)&Cp, g_C);

    const dim3 gg(EMB / 128, NTOK / 128);   // (8, 64)

    gemm_nt<1><<<gg, 256>>>(x, Wq, bq, Qp);
    gemm_nt<1><<<gg, 256>>>(x, Wk, bk, Kp);
    gemm_nt<1><<<gg, 256>>>(x, Wv, bv, Vp);

    const size_t attn_smem = (size_t)ATTN_SMEM_FLOATS * sizeof(float);
    cudaFuncSetAttribute(attn_kernel,
                         cudaFuncAttributeMaxDynamicSharedMemorySize,
                         (int)attn_smem);
    attn_kernel<<<dim3(SEQ / 128, NBH), 256, attn_smem>>>(Qp, Kp, Vp, Cp);

    gemm_nt<0><<<gg, 256>>>(Cp, Wo, bo, out);
}

// round 2
// speedup vs baseline: 2.6138x; 2.6138x over previous
#include <cuda_runtime.h>
#include <cstdint>

#define SEQ   2048
#define EMB   1024
#define NH    16
#define HD    64
#define NTOK  8192      // B*S
#define NBH   64        // B*H

// Scratch: Q,K,V in [B,H,S,D], ctx in [token,E].
__device__ float g_Q[(size_t)NTOK * EMB];
__device__ float g_K[(size_t)NTOK * EMB];
__device__ float g_V[(size_t)NTOK * EMB];
__device__ float g_C[(size_t)NTOK * EMB];

__device__ __forceinline__ uint32_t f2t(float x) {
    uint32_t r; asm("cvt.rna.tf32.f32 %0, %1;" : "=r"(r) : "f"(x)); return r;
}

// D += A(16x8,row) * B(8x8,col), tf32 in, fp32 acc
__device__ __forceinline__ void mma8(float* d, const uint32_t* a, const uint32_t* b) {
    asm volatile(
        "mma.sync.aligned.m16n8k8.row.col.f32.tf32.tf32.f32 "
        "{%0,%1,%2,%3}, {%4,%5,%6,%7}, {%8,%9}, {%0,%1,%2,%3};\n"
        : "+f"(d[0]), "+f"(d[1]), "+f"(d[2]), "+f"(d[3])
        : "r"(a[0]), "r"(a[1]), "r"(a[2]), "r"(a[3]), "r"(b[0]), "r"(b[1]));
}

// ---------------------------------------------------------------------------
// TF32 GEMM: C[m,n] = sum_k A[m,k]*W[n,k] + bias[n]
// 128x128 CTA tile, BK=16, 256 thr, warps 2x4, warp tile 64x32.
// smem k-major with swizzle: col' = col ^ (((k>>2)&3)<<3)  (conflict-free).
// ---------------------------------------------------------------------------
#define GSTR 136

template<int TRANS_OUT>
__global__ void __launch_bounds__(256, 2) gemm_tf32(
    const float* __restrict__ A, const float* __restrict__ W,
    const float* __restrict__ bias, float* __restrict__ Cout)
{
    __shared__ uint32_t As[16][GSTR];
    __shared__ uint32_t Bs[16][GSTR];

    const int tid  = threadIdx.x;
    const int bm   = blockIdx.y * 128;
    const int bn   = blockIdx.x * 128;
    const int lrow = tid >> 2;          // 0..63
    const int lcol = (tid & 3) << 2;    // 0,4,8,12  (k base)
    const int warp = tid >> 5, lane = tid & 31;
    const int wm = warp >> 2, wn = warp & 3;
    const int gid = lane >> 2, tq = lane & 3;

    const float* A0 = A + (size_t)(bm + lrow) * EMB + lcol;
    const float* A1 = A0 + (size_t)64 * EMB;
    const float* W0 = W + (size_t)(bn + lrow) * EMB + lcol;
    const float* W1 = W0 + (size_t)64 * EMB;

    // staging swizzle: all 4 k (lcol..lcol+3) share (k>>2)
    const int sx = ((lcol >> 2) & 3) << 3;
    const int m0s = lrow ^ sx;
    const int m1s = (lrow + 64) ^ sx;

    float acc[4][4][4];
#pragma unroll
    for (int i = 0; i < 4; i++)
#pragma unroll
        for (int j = 0; j < 4; j++)
#pragma unroll
            for (int v = 0; v < 4; v++) acc[i][j][v] = 0.f;

    for (int k0 = 0; k0 < EMB; k0 += 16) {
        float4 a0 = *(const float4*)(A0 + k0);
        float4 a1 = *(const float4*)(A1 + k0);
        float4 w0 = *(const float4*)(W0 + k0);
        float4 w1 = *(const float4*)(W1 + k0);
        __syncthreads();
        As[lcol+0][m0s] = f2t(a0.x); As[lcol+1][m0s] = f2t(a0.y);
        As[lcol+2][m0s] = f2t(a0.z); As[lcol+3][m0s] = f2t(a0.w);
        As[lcol+0][m1s] = f2t(a1.x); As[lcol+1][m1s] = f2t(a1.y);
        As[lcol+2][m1s] = f2t(a1.z); As[lcol+3][m1s] = f2t(a1.w);
        Bs[lcol+0][m0s] = f2t(w0.x); Bs[lcol+1][m0s] = f2t(w0.y);
        Bs[lcol+2][m0s] = f2t(w0.z); Bs[lcol+3][m0s] = f2t(w0.w);
        Bs[lcol+0][m1s] = f2t(w1.x); Bs[lcol+1][m1s] = f2t(w1.y);
        Bs[lcol+2][m1s] = f2t(w1.z); Bs[lcol+3][m1s] = f2t(w1.w);
        __syncthreads();

#pragma unroll
        for (int ks = 0; ks < 2; ks++) {
            const int kk = ks * 8;
            const int xa = ((kk >> 2) & 3) << 3;          // swizzle for k in [kk,kk+4)
            const int xb = (((kk + 4) >> 2) & 3) << 3;    // for k in [kk+4,kk+8)
            uint32_t af[4][4], bf[4][2];
#pragma unroll
            for (int mt = 0; mt < 4; mt++) {
                const int m0 = wm * 64 + mt * 16;
                af[mt][0] = As[kk+tq  ][(m0+gid  ) ^ xa];
                af[mt][1] = As[kk+tq  ][(m0+gid+8) ^ xa];
                af[mt][2] = As[kk+tq+4][(m0+gid  ) ^ xb];
                af[mt][3] = As[kk+tq+4][(m0+gid+8) ^ xb];
            }
#pragma unroll
            for (int nt = 0; nt < 4; nt++) {
                const int n0 = wn * 32 + nt * 8;
                bf[nt][0] = Bs[kk+tq  ][(n0+gid) ^ xa];
                bf[nt][1] = Bs[kk+tq+4][(n0+gid) ^ xb];
            }
#pragma unroll
            for (int mt = 0; mt < 4; mt++)
#pragma unroll
                for (int nt = 0; nt < 4; nt++)
                    mma8(acc[mt][nt], af[mt], bf[nt]);
        }
    }

    // Epilogue
#pragma unroll
    for (int mt = 0; mt < 4; mt++) {
#pragma unroll
        for (int nt = 0; nt < 4; nt++) {
            const int m_ = bm + wm * 64 + mt * 16 + gid;
            const int n_ = bn + wn * 32 + nt * 8 + 2 * tq;
            const float bz0 = bias[n_], bz1 = bias[n_ + 1];
            float c00 = acc[mt][nt][0] + bz0;
            float c01 = acc[mt][nt][1] + bz1;
            float c10 = acc[mt][nt][2] + bz0;
            float c11 = acc[mt][nt][3] + bz1;
            if (TRANS_OUT) {
                const int b = m_ >> 11, s = m_ & (SEQ - 1);
                const int h = n_ >> 6,  d = n_ & 63;
                float2* p0 = (float2*)&Cout[((size_t)(b*NH+h)*SEQ + s) * HD + d];
                float2* p1 = (float2*)&Cout[((size_t)(b*NH+h)*SEQ + s + 8) * HD + d];
                *p0 = make_float2(c00, c01);
                *p1 = make_float2(c10, c11);
            } else {
                *(float2*)&Cout[(size_t)m_ * EMB + n_]       = make_float2(c00, c01);
                *(float2*)&Cout[(size_t)(m_ + 8) * EMB + n_] = make_float2(c10, c11);
            }
        }
    }
}

// ---------------------------------------------------------------------------
// Fused attention, TF32 MMA. 128-query tile per CTA, stream 128-key tiles.
//   S = Q·K^T ; P = S / (8 + |S|)  (1/sqrt(64) folded) ; ctx += P·V
// ---------------------------------------------------------------------------
#define QK_STR 136            // Qs/Ks/Ps row stride (words)
#define V_STR  72             // Vs row stride
#define QS_OFF 0
#define KS_OFF (64 * QK_STR)
#define VS_OFF (KS_OFF + 64 * QK_STR)
#define PS_OFF (VS_OFF + 128 * V_STR)
#define ATTN_SMEM_WORDS (PS_OFF + 128 * QK_STR)

__global__ void __launch_bounds__(256, 1) attn_tf32(
    const float* __restrict__ Q, const float* __restrict__ K,
    const float* __restrict__ V, float* __restrict__ Cctx)
{
    extern __shared__ uint32_t sm[];
    uint32_t* Qs = sm + QS_OFF;   // [d][i] swizzled
    uint32_t* Ks = sm + KS_OFF;   // [d][j] swizzled
    uint32_t* Vs = sm + VS_OFF;   // [j][d] natural
    uint32_t* Ps = sm + PS_OFF;   // [j][i]

    const int tid  = threadIdx.x;
    const int warp = tid >> 5, lane = tid & 31;
    const int gid  = lane >> 2, tq = lane & 3;
    const int wm1 = warp >> 2, wn1 = warp & 3;    // gemm1: 2x4, warp tile 64x32
    const int wm2 = warp >> 1, wn2 = warp & 1;    // gemm2: 4x2, warp tile 32x32
    const int bh = blockIdx.y;
    const int q0 = blockIdx.x * 128;

    const float* Qbh = Q + (size_t)bh * SEQ * HD;
    const float* Kbh = K + (size_t)bh * SEQ * HD;
    const float* Vbh = V + (size_t)bh * SEQ * HD;

    // Load Q tile -> Qs[d][i ^ ((d>>2)&15)]
    {
        int idx = tid;
#pragma unroll
        for (int r = 0; r < 8; r++, idx += 256) {
            const int row = idx >> 4;
            const int d0  = (idx & 15) << 2;
            const int xr  = row ^ ((d0 >> 2) & 15);
            float4 v = *(const float4*)(Qbh + (size_t)(q0 + row) * HD + d0);
            Qs[(d0+0)*QK_STR + xr] = f2t(v.x);
            Qs[(d0+1)*QK_STR + xr] = f2t(v.y);
            Qs[(d0+2)*QK_STR + xr] = f2t(v.z);
            Qs[(d0+3)*QK_STR + xr] = f2t(v.w);
        }
    }

    float acc2[2][4][4];
#pragma unroll
    for (int i = 0; i < 2; i++)
#pragma unroll
        for (int j = 0; j < 4; j++)
#pragma unroll
            for (int v = 0; v < 4; v++) acc2[i][j][v] = 0.f;

#pragma unroll 1
    for (int kt = 0; kt < SEQ; kt += 128) {
        __syncthreads();   // prev iter done with Ks/Vs/Ps
        // Load K (transposed+swizzled) and V (natural) tiles
        {
            int idx = tid;
#pragma unroll
            for (int r = 0; r < 8; r++, idx += 256) {
                const int row = idx >> 4;
                const int d0  = (idx & 15) << 2;
                const int xr  = row ^ ((d0 >> 2) & 15);
                float4 kv = *(const float4*)(Kbh + (size_t)(kt + row) * HD + d0);
                Ks[(d0+0)*QK_STR + xr] = f2t(kv.x);
                Ks[(d0+1)*QK_STR + xr] = f2t(kv.y);
                Ks[(d0+2)*QK_STR + xr] = f2t(kv.z);
                Ks[(d0+3)*QK_STR + xr] = f2t(kv.w);
                float4 vv = *(const float4*)(Vbh + (size_t)(kt + row) * HD + d0);
                uint4 vt = make_uint4(f2t(vv.x), f2t(vv.y), f2t(vv.z), f2t(vv.w));
                *(uint4*)&Vs[row * V_STR + d0] = vt;
            }
        }
        __syncthreads();

        // gemm1: S[i][j] = sum_d Q[i][d] K[j][d]
        float acc1[4][4][4];
#pragma unroll
        for (int i = 0; i < 4; i++)
#pragma unroll
            for (int j = 0; j < 4; j++)
#pragma unroll
                for (int v = 0; v < 4; v++) acc1[i][j][v] = 0.f;

#pragma unroll 2
        for (int ks = 0; ks < 8; ks++) {
            const int kk = ks * 8;
            const int xa = (kk >> 2) & 15;
            const int xb = ((kk + 4) >> 2) & 15;
            uint32_t af[4][4], bf[4][2];
#pragma unroll
            for (int mt = 0; mt < 4; mt++) {
                const int m0 = wm1 * 64 + mt * 16;
                af[mt][0] = Qs[(kk+tq  )*QK_STR + ((m0+gid  ) ^ xa)];
                af[mt][1] = Qs[(kk+tq  )*QK_STR + ((m0+gid+8) ^ xa)];
                af[mt][2] = Qs[(kk+tq+4)*QK_STR + ((m0+gid  ) ^ xb)];
                af[mt][3] = Qs[(kk+tq+4)*QK_STR + ((m0+gid+8) ^ xb)];
            }
#pragma unroll
            for (int nt = 0; nt < 4; nt++) {
                const int n0 = wn1 * 32 + nt * 8;
                bf[nt][0] = Ks[(kk+tq  )*QK_STR + ((n0+gid) ^ xa)];
                bf[nt][1] = Ks[(kk+tq+4)*QK_STR + ((n0+gid) ^ xb)];
            }
#pragma unroll
            for (int mt = 0; mt < 4; mt++)
#pragma unroll
                for (int nt = 0; nt < 4; nt++)
                    mma8(acc1[mt][nt], af[mt], bf[nt]);
        }

        // softsign (scale 1/8 folded) -> Ps[j][i] in tf32
#pragma unroll
        for (int mt = 0; mt < 4; mt++) {
#pragma unroll
            for (int nt = 0; nt < 4; nt++) {
                const int row = wm1 * 64 + mt * 16 + gid;
                const int col = wn1 * 32 + nt * 8 + 2 * tq;
                float s0 = acc1[mt][nt][0], s1 = acc1[mt][nt][1];
                float s2 = acc1[mt][nt][2], s3 = acc1[mt][nt][3];
                Ps[(col  )*QK_STR + row    ] = f2t(s0 / (8.f + fabsf(s0)));
                Ps[(col+1)*QK_STR + row    ] = f2t(s1 / (8.f + fabsf(s1)));
                Ps[(col  )*QK_STR + row + 8] = f2t(s2 / (8.f + fabsf(s2)));
                Ps[(col+1)*QK_STR + row + 8] = f2t(s3 / (8.f + fabsf(s3)));
            }
        }
        __syncthreads();

        // gemm2: ctx[i][d] += sum_j P[i][j] V[j][d]
#pragma unroll 2
        for (int ks = 0; ks < 16; ks++) {
            const int kk = ks * 8;
            uint32_t af[2][4], bf[4][2];
#pragma unroll
            for (int mt = 0; mt < 2; mt++) {
                const int i0 = wm2 * 32 + mt * 16;
                af[mt][0] = Ps[(kk+tq  )*QK_STR + i0+gid  ];
                af[mt][1] = Ps[(kk+tq  )*QK_STR + i0+gid+8];
                af[mt][2] = Ps[(kk+tq+4)*QK_STR + i0+gid  ];
                af[mt][3] = Ps[(kk+tq+4)*QK_STR + i0+gid+8];
            }
#pragma unroll
            for (int nt = 0; nt < 4; nt++) {
                const int d0 = wn2 * 32 + nt * 8;
                bf[nt][0] = Vs[(kk+tq  )*V_STR + d0+gid];
                bf[nt][1] = Vs[(kk+tq+4)*V_STR + d0+gid];
            }
#pragma unroll
            for (int mt = 0; mt < 2; mt++)
#pragma unroll
                for (int nt = 0; nt < 4; nt++)
                    mma8(acc2[mt][nt], af[mt], bf[nt]);
        }
    }

    // Epilogue: ctx -> [token, E]
    const int b = bh >> 4, h = bh & 15;
#pragma unroll
    for (int mt = 0; mt < 2; mt++) {
#pragma unroll
        for (int nt = 0; nt < 4; nt++) {
            const int i = wm2 * 32 + mt * 16 + gid;
            const int d = wn2 * 32 + nt * 8 + 2 * tq;
            float* base0 = &Cctx[(size_t)(b * SEQ + q0 + i    ) * EMB + h * HD + d];
            float* base1 = &Cctx[(size_t)(b * SEQ + q0 + i + 8) * EMB + h * HD + d];
            *(float2*)base0 = make_float2(acc2[mt][nt][0], acc2[mt][nt][1]);
            *(float2*)base1 = make_float2(acc2[mt][nt][2], acc2[mt][nt][3]);
        }
    }
}

// ---------------------------------------------------------------------------
extern "C" void kernel_launch(void* const* d_in, const int* in_sizes, int n_in,
                              void* d_out, int out_size)
{
    (void)in_sizes; (void)n_in; (void)out_size;
    const float* x  = (const float*)d_in[0];
    const float* Wq = (const float*)d_in[1];
    const float* bq = (const float*)d_in[2];
    const float* Wk = (const float*)d_in[3];
    const float* bk = (const float*)d_in[4];
    const float* Wv = (const float*)d_in[5];
    const float* bv = (const float*)d_in[6];
    const float* Wo = (const float*)d_in[7];
    const float* bo = (const float*)d_in[8];
    float* out = (float*)d_out;

    float *Qp, *Kp, *Vp, *Cp;
    cudaGetSymbolAddress((void**)&Qp, g_Q);
    cudaGetSymbolAddress((void**)&Kp, g_K);
    cudaGetSymbolAddress((void**)&Vp, g_V);
    cudaGetSymbolAddress((void**)&Cp, g_C);

    const dim3 gg(EMB / 128, NTOK / 128);   // (8, 64)

    gemm_tf32<1><<<gg, 256>>>(x, Wq, bq, Qp);
    gemm_tf32<1><<<gg, 256>>>(x, Wk, bk, Kp);
    gemm_tf32<1><<<gg, 256>>>(x, Wv, bv, Vp);

    const size_t attn_smem = (size_t)ATTN_SMEM_WORDS * sizeof(uint32_t);
    cudaFuncSetAttribute(attn_tf32,
                         cudaFuncAttributeMaxDynamicSharedMemorySize,
                         (int)attn_smem);
    attn_tf32<<<dim3(SEQ / 128, NBH), 256, attn_smem>>>(Qp, Kp, Vp, Cp);

    gemm_tf32<0><<<gg, 256>>>(Cp, Wo, bo, out);
}

// round 3
// speedup vs baseline: 3.1247x; 1.1955x over previous
#include <cuda_runtime.h>
#include <cstdint>

#define SEQ   2048
#define EMB   1024
#define NH    16
#define HD    64
#define NTOK  8192      // B*S
#define NBH   64        // B*H

__device__ float g_Q[(size_t)NTOK * EMB];
__device__ float g_K[(size_t)NTOK * EMB];
__device__ float g_V[(size_t)NTOK * EMB];
__device__ float g_C[(size_t)NTOK * EMB];

__device__ __forceinline__ uint32_t f2t(float x) {
    uint32_t r; asm("cvt.rna.tf32.f32 %0, %1;" : "=r"(r) : "f"(x)); return r;
}

__device__ __forceinline__ void mma8(float* d, const uint32_t* a, const uint32_t* b) {
    asm volatile(
        "mma.sync.aligned.m16n8k8.row.col.f32.tf32.tf32.f32 "
        "{%0,%1,%2,%3}, {%4,%5,%6,%7}, {%8,%9}, {%0,%1,%2,%3};\n"
        : "+f"(d[0]), "+f"(d[1]), "+f"(d[2]), "+f"(d[3])
        : "r"(a[0]), "r"(a[1]), "r"(a[2]), "r"(a[3]), "r"(b[0]), "r"(b[1]));
}

// ===========================================================================
// TF32 GEMM, double-buffered software pipeline.
// C[m,n] = sum_k A[m,k]*W[n,k] + bias[n]; 128x128 CTA tile, BK=16, 256 thr.
// ===========================================================================
#define GSTR 136

struct GemmSmem {
    uint32_t As[2][16][GSTR];
    uint32_t Bs[2][16][GSTR];
};

__device__ __forceinline__ void gemm_stage(
    uint32_t (*As)[GSTR], uint32_t (*Bs)[GSTR],
    const float4& a0, const float4& a1, const float4& w0, const float4& w1,
    int lcol, int m0s, int m1s)
{
    As[lcol+0][m0s] = f2t(a0.x); As[lcol+1][m0s] = f2t(a0.y);
    As[lcol+2][m0s] = f2t(a0.z); As[lcol+3][m0s] = f2t(a0.w);
    As[lcol+0][m1s] = f2t(a1.x); As[lcol+1][m1s] = f2t(a1.y);
    As[lcol+2][m1s] = f2t(a1.z); As[lcol+3][m1s] = f2t(a1.w);
    Bs[lcol+0][m0s] = f2t(w0.x); Bs[lcol+1][m0s] = f2t(w0.y);
    Bs[lcol+2][m0s] = f2t(w0.z); Bs[lcol+3][m0s] = f2t(w0.w);
    Bs[lcol+0][m1s] = f2t(w1.x); Bs[lcol+1][m1s] = f2t(w1.y);
    Bs[lcol+2][m1s] = f2t(w1.z); Bs[lcol+3][m1s] = f2t(w1.w);
}

__device__ __forceinline__ void gemm_compute(
    const uint32_t (*As)[GSTR], const uint32_t (*Bs)[GSTR],
    int wm, int wn, int gid, int tq, float acc[4][4][4])
{
#pragma unroll
    for (int ks = 0; ks < 2; ks++) {
        const int kk = ks * 8;
        const int xa = ((kk >> 2) & 3) << 3;
        const int xb = (((kk + 4) >> 2) & 3) << 3;
        uint32_t af[4][4], bf[4][2];
#pragma unroll
        for (int mt = 0; mt < 4; mt++) {
            const int m0 = wm * 64 + mt * 16;
            af[mt][0] = As[kk+tq  ][(m0+gid  ) ^ xa];
            af[mt][1] = As[kk+tq  ][(m0+gid+8) ^ xa];
            af[mt][2] = As[kk+tq+4][(m0+gid  ) ^ xb];
            af[mt][3] = As[kk+tq+4][(m0+gid+8) ^ xb];
        }
#pragma unroll
        for (int nt = 0; nt < 4; nt++) {
            const int n0 = wn * 32 + nt * 8;
            bf[nt][0] = Bs[kk+tq  ][(n0+gid) ^ xa];
            bf[nt][1] = Bs[kk+tq+4][(n0+gid) ^ xb];
        }
#pragma unroll
        for (int mt = 0; mt < 4; mt++)
#pragma unroll
            for (int nt = 0; nt < 4; nt++)
                mma8(acc[mt][nt], af[mt], bf[nt]);
    }
}

template<int TRANS_OUT>
__device__ __forceinline__ void gemm_body(
    const float* __restrict__ A, const float* __restrict__ W,
    const float* __restrict__ bias, float* __restrict__ Cout, GemmSmem& S)
{
    const int tid  = threadIdx.x;
    const int bm   = blockIdx.y * 128;
    const int bn   = blockIdx.x * 128;
    const int lrow = tid >> 2;
    const int lcol = (tid & 3) << 2;
    const int warp = tid >> 5, lane = tid & 31;
    const int wm = warp >> 2, wn = warp & 3;
    const int gid = lane >> 2, tq = lane & 3;

    const float* A0 = A + (size_t)(bm + lrow) * EMB + lcol;
    const float* A1 = A0 + (size_t)64 * EMB;
    const float* W0 = W + (size_t)(bn + lrow) * EMB + lcol;
    const float* W1 = W0 + (size_t)64 * EMB;

    const int sx  = ((lcol >> 2) & 3) << 3;
    const int m0s = lrow ^ sx;
    const int m1s = (lrow + 64) ^ sx;

    float acc[4][4][4];
#pragma unroll
    for (int i = 0; i < 4; i++)
#pragma unroll
        for (int j = 0; j < 4; j++)
#pragma unroll
            for (int v = 0; v < 4; v++) acc[i][j][v] = 0.f;

    // prologue: stage k0=0 into buffer 0
    float4 a0 = *(const float4*)(A0);
    float4 a1 = *(const float4*)(A1);
    float4 w0 = *(const float4*)(W0);
    float4 w1 = *(const float4*)(W1);
    gemm_stage(S.As[0], S.Bs[0], a0, a1, w0, w1, lcol, m0s, m1s);
    __syncthreads();

    int buf = 0;
#pragma unroll 1
    for (int k0 = 16; k0 < EMB; k0 += 16) {
        // issue next-tile loads early; latency hides under compute
        a0 = *(const float4*)(A0 + k0);
        a1 = *(const float4*)(A1 + k0);
        w0 = *(const float4*)(W0 + k0);
        w1 = *(const float4*)(W1 + k0);
        gemm_compute(S.As[buf], S.Bs[buf], wm, wn, gid, tq, acc);
        gemm_stage(S.As[buf^1], S.Bs[buf^1], a0, a1, w0, w1, lcol, m0s, m1s);
        __syncthreads();
        buf ^= 1;
    }
    gemm_compute(S.As[buf], S.Bs[buf], wm, wn, gid, tq, acc);

#pragma unroll
    for (int mt = 0; mt < 4; mt++) {
#pragma unroll
        for (int nt = 0; nt < 4; nt++) {
            const int m_ = bm + wm * 64 + mt * 16 + gid;
            const int n_ = bn + wn * 32 + nt * 8 + 2 * tq;
            const float bz0 = bias[n_], bz1 = bias[n_ + 1];
            float c00 = acc[mt][nt][0] + bz0;
            float c01 = acc[mt][nt][1] + bz1;
            float c10 = acc[mt][nt][2] + bz0;
            float c11 = acc[mt][nt][3] + bz1;
            if (TRANS_OUT) {
                const int b = m_ >> 11, s = m_ & (SEQ - 1);
                const int h = n_ >> 6,  d = n_ & 63;
                *(float2*)&Cout[((size_t)(b*NH+h)*SEQ + s) * HD + d]     = make_float2(c00, c01);
                *(float2*)&Cout[((size_t)(b*NH+h)*SEQ + s + 8) * HD + d] = make_float2(c10, c11);
            } else {
                *(float2*)&Cout[(size_t)m_ * EMB + n_]       = make_float2(c00, c01);
                *(float2*)&Cout[(size_t)(m_ + 8) * EMB + n_] = make_float2(c10, c11);
            }
        }
    }
}

__global__ void __launch_bounds__(256, 2) gemm_qkv(
    const float* __restrict__ x,
    const float* __restrict__ Wq, const float* __restrict__ bq, float* __restrict__ Qo,
    const float* __restrict__ Wk, const float* __restrict__ bk, float* __restrict__ Ko,
    const float* __restrict__ Wv, const float* __restrict__ bv, float* __restrict__ Vo)
{
    __shared__ GemmSmem S;
    if (blockIdx.z == 0)      gemm_body<1>(x, Wq, bq, Qo, S);
    else if (blockIdx.z == 1) gemm_body<1>(x, Wk, bk, Ko, S);
    else                      gemm_body<1>(x, Wv, bv, Vo, S);
}

__global__ void __launch_bounds__(256, 2) gemm_o(
    const float* __restrict__ A, const float* __restrict__ W,
    const float* __restrict__ bias, float* __restrict__ C)
{
    __shared__ GemmSmem S;
    gemm_body<0>(A, W, bias, C, S);
}

// ===========================================================================
// Fused attention, TF32 MMA, 512 threads (16 warps).
// 128-query tile per CTA; stream 128-key tiles.
//   S = Q·K^T ; P = S/(8+|S|) (1/sqrt(64) folded) ; ctx += P·V
// gemm1: warps 4x4, warp tile 32x32.  gemm2: warps 8x2, warp tile 16x32.
// ===========================================================================
#define QK_STR 136
#define V_STR  72
#define QS_OFF 0
#define KS_OFF (64 * QK_STR)
#define VS_OFF (KS_OFF + 64 * QK_STR)
#define PS_OFF (VS_OFF + 128 * V_STR)
#define ATTN_SMEM_WORDS (PS_OFF + 128 * QK_STR)

__global__ void __launch_bounds__(512, 1) attn_tf32(
    const float* __restrict__ Q, const float* __restrict__ K,
    const float* __restrict__ V, float* __restrict__ Cctx)
{
    extern __shared__ uint32_t sm[];
    uint32_t* Qs = sm + QS_OFF;   // [d][i] swizzled
    uint32_t* Ks = sm + KS_OFF;   // [d][j] swizzled
    uint32_t* Vs = sm + VS_OFF;   // [j][d] natural
    uint32_t* Ps = sm + PS_OFF;   // [j][i] transposed

    const int tid  = threadIdx.x;
    const int warp = tid >> 5, lane = tid & 31;
    const int gid  = lane >> 2, tq = lane & 3;
    const int wm1 = warp >> 2, wn1 = warp & 3;    // gemm1: 4x4
    const int wm2 = warp >> 1, wn2 = warp & 1;    // gemm2: 8x2
    const int bh = blockIdx.y;
    const int q0 = blockIdx.x * 128;

    const float* Qbh = Q + (size_t)bh * SEQ * HD;
    const float* Kbh = K + (size_t)bh * SEQ * HD;
    const float* Vbh = V + (size_t)bh * SEQ * HD;

    // Load Q tile -> Qs[d][i ^ ((d>>2)&15)]
    {
        int idx = tid;
#pragma unroll
        for (int r = 0; r < 4; r++, idx += 512) {
            const int row = idx >> 4;
            const int d0  = (idx & 15) << 2;
            const int xr  = row ^ ((d0 >> 2) & 15);
            float4 v = *(const float4*)(Qbh + (size_t)(q0 + row) * HD + d0);
            Qs[(d0+0)*QK_STR + xr] = f2t(v.x);
            Qs[(d0+1)*QK_STR + xr] = f2t(v.y);
            Qs[(d0+2)*QK_STR + xr] = f2t(v.z);
            Qs[(d0+3)*QK_STR + xr] = f2t(v.w);
        }
    }

    float acc2[4][4];
#pragma unroll
    for (int j = 0; j < 4; j++)
#pragma unroll
        for (int v = 0; v < 4; v++) acc2[j][v] = 0.f;

#pragma unroll 1
    for (int kt = 0; kt < SEQ; kt += 128) {
        __syncthreads();   // prev gemm2 done with Vs/Ps (covers Qs on iter 0)
        {
            int idx = tid;
#pragma unroll
            for (int r = 0; r < 4; r++, idx += 512) {
                const int row = idx >> 4;
                const int d0  = (idx & 15) << 2;
                const int xr  = row ^ ((d0 >> 2) & 15);
                float4 kv = *(const float4*)(Kbh + (size_t)(kt + row) * HD + d0);
                Ks[(d0+0)*QK_STR + xr] = f2t(kv.x);
                Ks[(d0+1)*QK_STR + xr] = f2t(kv.y);
                Ks[(d0+2)*QK_STR + xr] = f2t(kv.z);
                Ks[(d0+3)*QK_STR + xr] = f2t(kv.w);
                float4 vv = *(const float4*)(Vbh + (size_t)(kt + row) * HD + d0);
                uint4 vt = make_uint4(f2t(vv.x), f2t(vv.y), f2t(vv.z), f2t(vv.w));
                *(uint4*)&Vs[row * V_STR + d0] = vt;
            }
        }
        __syncthreads();

        // gemm1: S[i][j] = sum_d Q[i][d] K[j][d], warp tile 32x32
        float acc1[2][4][4];
#pragma unroll
        for (int i = 0; i < 2; i++)
#pragma unroll
            for (int j = 0; j < 4; j++)
#pragma unroll
                for (int v = 0; v < 4; v++) acc1[i][j][v] = 0.f;

#pragma unroll
        for (int ks = 0; ks < 8; ks++) {
            const int kk = ks * 8;
            const int xa = (kk >> 2) & 15;
            const int xb = ((kk + 4) >> 2) & 15;
            uint32_t af[2][4], bf[4][2];
#pragma unroll
            for (int mt = 0; mt < 2; mt++) {
                const int m0 = wm1 * 32 + mt * 16;
                af[mt][0] = Qs[(kk+tq  )*QK_STR + ((m0+gid  ) ^ xa)];
                af[mt][1] = Qs[(kk+tq  )*QK_STR + ((m0+gid+8) ^ xa)];
                af[mt][2] = Qs[(kk+tq+4)*QK_STR + ((m0+gid  ) ^ xb)];
                af[mt][3] = Qs[(kk+tq+4)*QK_STR + ((m0+gid+8) ^ xb)];
            }
#pragma unroll
            for (int nt = 0; nt < 4; nt++) {
                const int n0 = wn1 * 32 + nt * 8;
                bf[nt][0] = Ks[(kk+tq  )*QK_STR + ((n0+gid) ^ xa)];
                bf[nt][1] = Ks[(kk+tq+4)*QK_STR + ((n0+gid) ^ xb)];
            }
#pragma unroll
            for (int mt = 0; mt < 2; mt++)
#pragma unroll
                for (int nt = 0; nt < 4; nt++)
                    mma8(acc1[mt][nt], af[mt], bf[nt]);
        }

        // softsign -> Ps[j][i] (tf32)
#pragma unroll
        for (int mt = 0; mt < 2; mt++) {
#pragma unroll
            for (int nt = 0; nt < 4; nt++) {
                const int row = wm1 * 32 + mt * 16 + gid;
                const int col = wn1 * 32 + nt * 8 + 2 * tq;
                float s0 = acc1[mt][nt][0], s1 = acc1[mt][nt][1];
                float s2 = acc1[mt][nt][2], s3 = acc1[mt][nt][3];
                Ps[(col  )*QK_STR + row    ] = f2t(__fdividef(s0, 8.f + fabsf(s0)));
                Ps[(col+1)*QK_STR + row    ] = f2t(__fdividef(s1, 8.f + fabsf(s1)));
                Ps[(col  )*QK_STR + row + 8] = f2t(__fdividef(s2, 8.f + fabsf(s2)));
                Ps[(col+1)*QK_STR + row + 8] = f2t(__fdividef(s3, 8.f + fabsf(s3)));
            }
        }
        __syncthreads();

        // gemm2: ctx[i][d] += sum_j P[i][j] V[j][d], warp tile 16x32
#pragma unroll
        for (int ks = 0; ks < 16; ks++) {
            const int kk = ks * 8;
            uint32_t af[4], bf[4][2];
            const int i0 = wm2 * 16;
            af[0] = Ps[(kk+tq  )*QK_STR + i0+gid  ];
            af[1] = Ps[(kk+tq  )*QK_STR + i0+gid+8];
            af[2] = Ps[(kk+tq+4)*QK_STR + i0+gid  ];
            af[3] = Ps[(kk+tq+4)*QK_STR + i0+gid+8];
#pragma unroll
            for (int nt = 0; nt < 4; nt++) {
                const int d0 = wn2 * 32 + nt * 8;
                bf[nt][0] = Vs[(kk+tq  )*V_STR + d0+gid];
                bf[nt][1] = Vs[(kk+tq+4)*V_STR + d0+gid];
            }
#pragma unroll
            for (int nt = 0; nt < 4; nt++)
                mma8(acc2[nt], af, bf[nt]);
        }
    }

    // Epilogue: ctx -> [token, E]
    const int b = bh >> 4, h = bh & 15;
#pragma unroll
    for (int nt = 0; nt < 4; nt++) {
        const int i = wm2 * 16 + gid;
        const int d = wn2 * 32 + nt * 8 + 2 * tq;
        float* base0 = &Cctx[(size_t)(b * SEQ + q0 + i    ) * EMB + h * HD + d];
        float* base1 = &Cctx[(size_t)(b * SEQ + q0 + i + 8) * EMB + h * HD + d];
        *(float2*)base0 = make_float2(acc2[nt][0], acc2[nt][1]);
        *(float2*)base1 = make_float2(acc2[nt][2], acc2[nt][3]);
    }
}

// ===========================================================================
extern "C" void kernel_launch(void* const* d_in, const int* in_sizes, int n_in,
                              void* d_out, int out_size)
{
    (void)in_sizes; (void)n_in; (void)out_size;
    const float* x  = (const float*)d_in[0];
    const float* Wq = (const float*)d_in[1];
    const float* bq = (const float*)d_in[2];
    const float* Wk = (const float*)d_in[3];
    const float* bk = (const float*)d_in[4];
    const float* Wv = (const float*)d_in[5];
    const float* bv = (const float*)d_in[6];
    const float* Wo = (const float*)d_in[7];
    const float* bo = (const float*)d_in[8];
    float* out = (float*)d_out;

    float *Qp, *Kp, *Vp, *Cp;
    cudaGetSymbolAddress((void**)&Qp, g_Q);
    cudaGetSymbolAddress((void**)&Kp, g_K);
    cudaGetSymbolAddress((void**)&Vp, g_V);
    cudaGetSymbolAddress((void**)&Cp, g_C);

    gemm_qkv<<<dim3(EMB / 128, NTOK / 128, 3), 256>>>(
        x, Wq, bq, Qp, Wk, bk, Kp, Wv, bv, Vp);

    const size_t attn_smem = (size_t)ATTN_SMEM_WORDS * sizeof(uint32_t);
    cudaFuncSetAttribute(attn_tf32,
                         cudaFuncAttributeMaxDynamicSharedMemorySize,
                         (int)attn_smem);
    attn_tf32<<<dim3(SEQ / 128, NBH), 512, attn_smem>>>(Qp, Kp, Vp, Cp);

    gemm_o<<<dim3(EMB / 128, NTOK / 128), 256>>>(Cp, Wo, bo, out);
}